// round 3
// baseline (speedup 1.0000x reference)
#include <cuda_runtime.h>
#include <cuda_bf16.h>
#include <cstdint>

// Problem dims (fixed by reference)
#define BATCH 2048
#define NCOMB 64      // m
#define NSTR  512     // n
#define HID   1024
#define NITER 60
#define PITER 30

// ---------------- device scratch (no allocations allowed) ----------------
__device__ float g_H1[BATCH * HID];
__device__ float g_H2[BATCH * HID];
__device__ float g_Z [BATCH * NSTR];
__device__ float g_tau;

// sparse S: row lists (for a = S @ xbar) and col lists (for t = y_m @ S)
// pair.x = __int_as_float(index), pair.y = value
__device__ float2 g_rowPair[NCOMB * NSTR];
__device__ int    g_rowCnt [NCOMB];
__device__ float2 g_colPair[NSTR * NCOMB];
__device__ int    g_colCnt [NSTR];

// ---------------- fp32 tiled GEMM:  C = relu(A @ B + bias) ----------------
// A: [M,K] row-major, B: [K,N] row-major, C: [M,N]
template<int BM, int BN, int BK, int TM, int TN>
__global__ void gemm_bias_relu(const float* __restrict__ A,
                               const float* __restrict__ B,
                               const float* __restrict__ bias,
                               float* __restrict__ C,
                               int M, int N, int K)
{
    constexpr int THREADS = (BM / TM) * (BN / TN);
    __shared__ float As[BK][BM];
    __shared__ float Bs[BK][BN];

    const int brow = blockIdx.y;
    const int bcol = blockIdx.x;
    A += brow * BM * K;
    B += bcol * BN;
    C += (size_t)brow * BM * N + bcol * BN;

    const int tid  = threadIdx.x;
    const int tcol = tid % (BN / TN);
    const int trow = tid / (BN / TN);

    // A loader: BK/4 float4 per row
    const int aRow      = tid / (BK / 4);
    const int aCol4     = tid % (BK / 4);
    const int aRowStr   = THREADS / (BK / 4);
    // B loader
    const int bRow      = tid / (BN / 4);
    const int bCol4     = tid % (BN / 4);
    const int bRowStr   = THREADS / (BN / 4);

    float acc[TM][TN];
    #pragma unroll
    for (int i = 0; i < TM; i++)
        #pragma unroll
        for (int j = 0; j < TN; j++) acc[i][j] = 0.f;

    float regM[TM], regN[TN];

    for (int k0 = 0; k0 < K; k0 += BK) {
        #pragma unroll
        for (int r = aRow; r < BM; r += aRowStr) {
            float4 t = *reinterpret_cast<const float4*>(A + (size_t)r * K + k0 + aCol4 * 4);
            As[aCol4 * 4 + 0][r] = t.x;
            As[aCol4 * 4 + 1][r] = t.y;
            As[aCol4 * 4 + 2][r] = t.z;
            As[aCol4 * 4 + 3][r] = t.w;
        }
        #pragma unroll
        for (int r = bRow; r < BK; r += bRowStr) {
            *reinterpret_cast<float4*>(&Bs[r][bCol4 * 4]) =
                *reinterpret_cast<const float4*>(B + (size_t)(k0 + r) * N + bCol4 * 4);
        }
        __syncthreads();

        #pragma unroll
        for (int k = 0; k < BK; k++) {
            #pragma unroll
            for (int i = 0; i < TM; i++) regM[i] = As[k][trow * TM + i];
            #pragma unroll
            for (int j = 0; j < TN; j++) regN[j] = Bs[k][tcol * TN + j];
            #pragma unroll
            for (int i = 0; i < TM; i++)
                #pragma unroll
                for (int j = 0; j < TN; j++)
                    acc[i][j] = fmaf(regM[i], regN[j], acc[i][j]);
        }
        __syncthreads();
    }

    // epilogue: bias + relu, vectorized float4 stores
    #pragma unroll
    for (int i = 0; i < TM; i++) {
        #pragma unroll
        for (int j = 0; j < TN; j += 4) {
            int col = tcol * TN + j;
            float4 bs = *reinterpret_cast<const float4*>(bias + bcol * BN + col);
            float4 o;
            o.x = fmaxf(acc[i][j + 0] + bs.x, 0.f);
            o.y = fmaxf(acc[i][j + 1] + bs.y, 0.f);
            o.z = fmaxf(acc[i][j + 2] + bs.z, 0.f);
            o.w = fmaxf(acc[i][j + 3] + bs.w, 0.f);
            *reinterpret_cast<float4*>(C + (size_t)(trow * TM + i) * N + col) = o;
        }
    }
}

// ---------------- build sparse CSR-ish lists from S ----------------
__global__ void build_sparse(const float* __restrict__ S)
{
    int tid = threadIdx.x;  // 512 threads, 1 block
    if (tid < NCOMB) {
        int c = 0;
        for (int j = 0; j < NSTR; j++) {
            float v = S[tid * NSTR + j];
            if (v != 0.f) {
                g_rowPair[tid * NSTR + c] = make_float2(__int_as_float(j), v);
                c++;
            }
        }
        g_rowCnt[tid] = c;
    }
    {
        int c = 0;
        for (int i = 0; i < NCOMB; i++) {
            float v = S[i * NSTR + tid];
            if (v != 0.f) {
                g_colPair[tid * NCOMB + c] = make_float2(__int_as_float(i), v);
                c++;
            }
        }
        g_colCnt[tid] = c;
    }
}

// ---------------- power iteration for L, tau = 0.9/L ----------------
// Mirrors: v2 = S^T (S v) + v; v = v2/||v2||; x30, then L = sqrt(v . (S^T(Sv)+v))
__global__ void power_iter(const float* __restrict__ S)
{
    __shared__ float v[NSTR];
    __shared__ float u[NCOMB];
    __shared__ float red[16];

    const int tid = threadIdx.x;       // 512
    const int w = tid >> 5, l = tid & 31;

    v[tid] = 0.04419417382415922f;     // 1/sqrt(512)
    __syncthreads();

    for (int step = 0; step <= PITER; step++) {
        // u = S @ v : warp w handles rows 4w..4w+3
        #pragma unroll
        for (int r = 0; r < 4; r++) {
            int i = w * 4 + r;
            float p = 0.f;
            for (int j = l; j < NSTR; j += 32) p = fmaf(S[i * NSTR + j], v[j], p);
            #pragma unroll
            for (int o = 16; o > 0; o >>= 1) p += __shfl_xor_sync(0xffffffffu, p, o);
            if (l == 0) u[i] = p;
        }
        __syncthreads();

        // s = (S^T u)[tid] + v[tid]
        float s = v[tid];
        for (int i = 0; i < NCOMB; i++) s = fmaf(S[i * NSTR + tid], u[i], s);

        if (step < PITER) {
            float sq = s * s;
            #pragma unroll
            for (int o = 16; o > 0; o >>= 1) sq += __shfl_xor_sync(0xffffffffu, sq, o);
            if (l == 0) red[w] = sq;
            __syncthreads();
            float tot = 0.f;
            #pragma unroll
            for (int r = 0; r < 16; r++) tot += red[r];
            float nrm = sqrtf(tot);
            float nv = s / nrm;
            __syncthreads();           // protect red before next iteration reuse
            v[tid] = nv;
            __syncthreads();
        } else {
            // final: L = sqrt( v . s )
            float q = v[tid] * s;
            #pragma unroll
            for (int o = 16; o > 0; o >>= 1) q += __shfl_xor_sync(0xffffffffu, q, o);
            if (l == 0) red[w] = q;
            __syncthreads();
            if (tid == 0) {
                float tot = 0.f;
                #pragma unroll
                for (int r = 0; r < 16; r++) tot += red[r];
                g_tau = 0.9f / sqrtf(tot);
            }
        }
    }
}

// ---------------- PDHG solver: one CTA per batch row ----------------
// state: x, y_n, Z, d in registers (4 cols/thread); xbar, y_m in smem
__global__ void __launch_bounds__(128) pdhg_solver(const float* __restrict__ Zg,
                                                   const float* __restrict__ Xflat,
                                                   float* __restrict__ out)
{
    const int row = blockIdx.x;
    const int tid = threadIdx.x;

    __shared__ float xbar[NSTR];
    __shared__ float ym[NCOMB];
    __shared__ float red[4];

    const float tau = g_tau;
    const float sigma = tau;

    float x[4], yn[4], z[4];
    #pragma unroll
    for (int k = 0; k < 4; k++) {
        int j = tid + 128 * k;
        z[k] = Zg[(size_t)row * NSTR + j];
        x[k] = 0.f;
        yn[k] = 0.f;
        xbar[j] = 0.f;
    }

    const int i = tid >> 1;
    const int h = tid & 1;
    const float bc = Xflat[row * NCOMB + i];
    const int rcnt = g_rowCnt[i];
    float ymr = 0.f;
    if (h == 0) ym[i] = 0.f;

    int ccnt[4];
    #pragma unroll
    for (int k = 0; k < 4; k++) ccnt[k] = g_colCnt[tid + 128 * k];

    for (int it = 0; it < NITER; it++) {
        __syncthreads();   // xbar (and ym-read of prev iter) settled

        // ---- step 1: a = S @ xbar ; y_m = max(y_m + sigma*(a - b), 0)
        float s = 0.f;
        const float2* rp = g_rowPair + i * NSTR;
        for (int e = h; e < rcnt; e += 2) {
            float2 p = rp[e];
            s = fmaf(p.y, xbar[__float_as_int(p.x)], s);
        }
        s += __shfl_xor_sync(0xffffffffu, s, 1);
        if (h == 0) {
            ymr = fmaxf(ymr + sigma * (s - bc), 0.f);
            ym[i] = ymr;
        }

        // ---- step 2: y_n = max(y_n - sigma*xbar, 0)
        #pragma unroll
        for (int k = 0; k < 4; k++) {
            int j = tid + 128 * k;
            yn[k] = fmaxf(yn[k] - sigma * xbar[j], 0.f);
        }
        __syncthreads();   // ym visible to all

        // ---- step 3+4: t = y_m @ S - y_n ; prox
        float d[4];
        float dd = 0.f;
        #pragma unroll
        for (int k = 0; k < 4; k++) {
            int j = tid + 128 * k;
            float t = -yn[k];
            const float2* cp = g_colPair + j * NCOMB;
            int cc = ccnt[k];
            for (int e = 0; e < cc; e++) {
                float2 p = cp[e];
                t = fmaf(p.y, ym[__float_as_int(p.x)], t);
            }
            float v = x[k] - tau * t + tau;   // (x - tau*KTy) + tau*W, W=1
            d[k] = v - z[k];
            dd = fmaf(d[k], d[k], dd);
        }
        // block reduce dd over 128 threads
        #pragma unroll
        for (int o = 16; o > 0; o >>= 1) dd += __shfl_xor_sync(0xffffffffu, dd, o);
        if ((tid & 31) == 0) red[tid >> 5] = dd;
        __syncthreads();
        float tot = red[0] + red[1] + red[2] + red[3];
        float nrm = sqrtf(tot);
        float scale = fmaxf(1.f - tau / fmaxf(nrm, 1e-12f), 0.f);

        #pragma unroll
        for (int k = 0; k < 4; k++) {
            int j = tid + 128 * k;
            float xn = z[k] + scale * d[k];
            xbar[j] = 2.f * xn - x[k];
            x[k] = xn;
        }
    }

    #pragma unroll
    for (int k = 0; k < 4; k++) {
        int j = tid + 128 * k;
        out[(size_t)row * NSTR + j] = x[k];
    }
}

// ---------------- launcher ----------------
extern "C" void kernel_launch(void* const* d_in, const int* in_sizes, int n_in,
                              void* d_out, int out_size)
{
    (void)in_sizes; (void)n_in; (void)out_size;
    const float* X  = (const float*)d_in[0];  // [2048,64] flattened
    const float* W1 = (const float*)d_in[1];  // [64,1024]
    const float* b1 = (const float*)d_in[2];
    const float* W2 = (const float*)d_in[3];  // [1024,1024]
    const float* b2 = (const float*)d_in[4];
    const float* W3 = (const float*)d_in[5];  // [1024,512]
    const float* b3 = (const float*)d_in[6];
    const float* S  = (const float*)d_in[7];  // [64,512]
    float* out = (float*)d_out;               // [2048,512]

    float *H1, *H2, *Z;
    cudaGetSymbolAddress((void**)&H1, g_H1);
    cudaGetSymbolAddress((void**)&H2, g_H2);
    cudaGetSymbolAddress((void**)&Z,  g_Z);

    // MLP: relu after every layer
    {   // L1: [2048,64] @ [64,1024]
        dim3 grid(HID / 64, BATCH / 64);
        gemm_bias_relu<64, 64, 8, 8, 4><<<grid, 128>>>(X, W1, b1, H1, BATCH, HID, NCOMB);
    }
    {   // L2: [2048,1024] @ [1024,1024]
        dim3 grid(HID / 64, BATCH / 128);
        gemm_bias_relu<128, 64, 8, 8, 4><<<grid, 256>>>(H1, W2, b2, H2, BATCH, HID, HID);
    }
    {   // L3: [2048,1024] @ [1024,512]
        dim3 grid(NSTR / 64, BATCH / 64);
        gemm_bias_relu<64, 64, 8, 8, 4><<<grid, 128>>>(H2, W3, b3, Z, BATCH, NSTR, HID);
    }

    build_sparse<<<1, 512>>>(S);
    power_iter<<<1, 512>>>(S);
    pdhg_solver<<<BATCH, 128>>>(Z, X, out);
}

// round 6
// speedup vs baseline: 1.5740x; 1.5740x over previous
#include <cuda_runtime.h>
#include <cuda_bf16.h>
#include <cstdint>

#define BATCH 2048
#define NCOMB 64
#define NSTR  512
#define HID   1024
#define NITER 60
#define PITER 30

// ---------------- device scratch ----------------
__device__ float g_H1[BATCH * HID];
__device__ float g_H2[BATCH * HID];
__device__ float g_Z [BATCH * NSTR];
__device__ float g_tau;
__device__ unsigned long long g_rowMask[NCOMB][8];   // bit b of word w -> col w*64+b
__device__ unsigned long long g_colMask[NSTR];       // bit i -> row i

// ============ fp32 double-buffered tiled GEMM: C = relu(A@B + bias) ============
// A:[M,K] row-major, B:[K,N] row-major, C:[M,N]
template<int BM, int BN, int BK, int TM, int TN>
__global__ void __launch_bounds__((BM/TM)*(BN/TN))
gemm_bias_relu(const float* __restrict__ A, const float* __restrict__ B,
               const float* __restrict__ bias, float* __restrict__ C,
               int M, int N, int K)
{
    constexpr int THREADS = (BM/TM)*(BN/TN);
    constexpr int LDA = BM + 4;
    constexpr int NA = (BM*BK/4)/THREADS;   // float4 per thread (A tile)
    constexpr int NB = (BK*BN/4)/THREADS;   // float4 per thread (B tile)

    __shared__ float As[2][BK*LDA];
    __shared__ float Bs[2][BK*BN];

    const int brow = blockIdx.y, bcol = blockIdx.x;
    A += (size_t)brow * BM * K;
    B += bcol * BN;
    C += (size_t)brow * BM * N + bcol * BN;

    const int tid  = threadIdx.x;
    const int tcol = tid % (BN/TN);
    const int trow = tid / (BN/TN);

    const int aRow    = tid / (BK/4);
    const int aCol4   = tid % (BK/4);
    const int aRowStr = THREADS/(BK/4);
    const int bRow    = tid / (BN/4);
    const int bCol4   = tid % (BN/4);
    const int bRowStr = THREADS/(BN/4);

    float4 aReg[NA], bReg[NB];
    float acc[TM][TN];
    #pragma unroll
    for (int i = 0; i < TM; i++)
        #pragma unroll
        for (int j = 0; j < TN; j++) acc[i][j] = 0.f;

    auto loadG = [&](int k0) {
        #pragma unroll
        for (int q = 0; q < NA; q++)
            aReg[q] = *reinterpret_cast<const float4*>(A + (size_t)(aRow + q*aRowStr)*K + k0 + aCol4*4);
        #pragma unroll
        for (int q = 0; q < NB; q++)
            bReg[q] = *reinterpret_cast<const float4*>(B + (size_t)(k0 + bRow + q*bRowStr)*N + bCol4*4);
    };
    auto storeS = [&](int buf) {
        #pragma unroll
        for (int q = 0; q < NA; q++) {
            int r = aRow + q*aRowStr;
            As[buf][(aCol4*4+0)*LDA + r] = aReg[q].x;
            As[buf][(aCol4*4+1)*LDA + r] = aReg[q].y;
            As[buf][(aCol4*4+2)*LDA + r] = aReg[q].z;
            As[buf][(aCol4*4+3)*LDA + r] = aReg[q].w;
        }
        #pragma unroll
        for (int q = 0; q < NB; q++)
            *reinterpret_cast<float4*>(&Bs[buf][(bRow + q*bRowStr)*BN + bCol4*4]) = bReg[q];
    };

    const int nt = K / BK;
    loadG(0);
    storeS(0);
    __syncthreads();

    for (int kt = 0; kt < nt; kt++) {
        const int cur = kt & 1;
        if (kt + 1 < nt) loadG((kt+1)*BK);

        #pragma unroll
        for (int k = 0; k < BK; k++) {
            float regM[TM], regN[TN];
            float4 m0 = *reinterpret_cast<const float4*>(&As[cur][k*LDA + trow*TM]);
            float4 m1 = *reinterpret_cast<const float4*>(&As[cur][k*LDA + trow*TM + 4]);
            regM[0]=m0.x; regM[1]=m0.y; regM[2]=m0.z; regM[3]=m0.w;
            regM[4]=m1.x; regM[5]=m1.y; regM[6]=m1.z; regM[7]=m1.w;
            float4 n0 = *reinterpret_cast<const float4*>(&Bs[cur][k*BN + tcol*TN]);
            float4 n1 = *reinterpret_cast<const float4*>(&Bs[cur][k*BN + tcol*TN + 4]);
            regN[0]=n0.x; regN[1]=n0.y; regN[2]=n0.z; regN[3]=n0.w;
            regN[4]=n1.x; regN[5]=n1.y; regN[6]=n1.z; regN[7]=n1.w;
            #pragma unroll
            for (int i = 0; i < TM; i++)
                #pragma unroll
                for (int j = 0; j < TN; j++)
                    acc[i][j] = fmaf(regM[i], regN[j], acc[i][j]);
        }

        if (kt + 1 < nt) { storeS(cur ^ 1); __syncthreads(); }
    }

    #pragma unroll
    for (int i = 0; i < TM; i++) {
        #pragma unroll
        for (int j = 0; j < TN; j += 4) {
            int col = tcol*TN + j;
            float4 bs = *reinterpret_cast<const float4*>(bias + bcol*BN + col);
            float4 o;
            o.x = fmaxf(acc[i][j+0] + bs.x, 0.f);
            o.y = fmaxf(acc[i][j+1] + bs.y, 0.f);
            o.z = fmaxf(acc[i][j+2] + bs.z, 0.f);
            o.w = fmaxf(acc[i][j+3] + bs.w, 0.f);
            *reinterpret_cast<float4*>(C + (size_t)(trow*TM + i)*N + col) = o;
        }
    }
}

// ============ fused: build bitmasks + power iteration (tau) ============
__global__ void __launch_bounds__(512) build_power(const float* __restrict__ S)
{
    __shared__ float v[NSTR];
    __shared__ float u[NCOMB];
    __shared__ float red[16];

    const int tid = threadIdx.x;           // 512
    const int lane = tid & 31, warp = tid >> 5;

    // row masks via ballot: warp handles rows warp, warp+16, +32, +48
    for (int i = warp; i < NCOMB; i += 16) {
        unsigned myb = 0;
        #pragma unroll
        for (int c = 0; c < 16; c++) {
            unsigned bal = __ballot_sync(0xffffffffu, S[i*NSTR + c*32 + lane] != 0.f);
            if (lane == c) myb = bal;
        }
        unsigned lo = __shfl_sync(0xffffffffu, myb, (lane & 7)*2);
        unsigned hi = __shfl_sync(0xffffffffu, myb, (lane & 7)*2 + 1);
        if (lane < 8)
            g_rowMask[i][lane] = (unsigned long long)lo | ((unsigned long long)hi << 32);
    }
    // col masks: thread j, coalesced column reads
    unsigned long long cmask = 0;
    for (int i = 0; i < NCOMB; i++)
        if (S[i*NSTR + tid] != 0.f) cmask |= (1ull << i);
    g_colMask[tid] = cmask;

    v[tid] = 0.04419417382415922f;   // 1/sqrt(512)
    __syncthreads();

    unsigned long long rm8[8];
    if (tid < NCOMB) {
        #pragma unroll
        for (int w = 0; w < 8; w++) rm8[w] = g_rowMask[tid][w];
    }
    __syncthreads();

    for (int step = 0; step <= PITER; step++) {
        if (tid < NCOMB) {
            float acc = 0.f;
            #pragma unroll
            for (int w = 0; w < 8; w++) {
                unsigned long long mm = rm8[w];
                while (mm) { int b = __ffsll(mm) - 1; mm &= mm - 1; acc += v[w*64 + b]; }
            }
            u[tid] = acc;
        }
        __syncthreads();
        float s = v[tid];
        {
            unsigned long long mm = cmask;
            while (mm) { int b = __ffsll(mm) - 1; mm &= mm - 1; s += u[b]; }
        }
        if (step < PITER) {
            float sq = s * s;
            #pragma unroll
            for (int o = 16; o > 0; o >>= 1) sq += __shfl_xor_sync(0xffffffffu, sq, o);
            if (lane == 0) red[warp] = sq;
            __syncthreads();
            float tot = 0.f;
            #pragma unroll
            for (int r = 0; r < 16; r++) tot += red[r];
            float nv = s / sqrtf(tot);
            __syncthreads();
            v[tid] = nv;
            __syncthreads();
        } else {
            float q = v[tid] * s;
            #pragma unroll
            for (int o = 16; o > 0; o >>= 1) q += __shfl_xor_sync(0xffffffffu, q, o);
            if (lane == 0) red[warp] = q;
            __syncthreads();
            if (tid == 0) {
                float tot = 0.f;
                for (int r = 0; r < 16; r++) tot += red[r];
                g_tau = 0.9f / sqrtf(tot);
            }
        }
    }
}

// ============ PDHG solver: 4 batch rows per CTA, mask-driven float4 gathers ====
__global__ void __launch_bounds__(128) pdhg_solver(const float* __restrict__ Zg,
                                                   const float* __restrict__ Xf,
                                                   float* __restrict__ out)
{
    const int r0  = blockIdx.x * 4;
    const int tid = threadIdx.x;
    const int lane = tid & 31, warp = tid >> 5;

    __shared__ float4 xbar[NSTR];    // [j] -> 4 batch rows
    __shared__ float4 ym[NCOMB];
    __shared__ float4 red4[4];

    const float tau = g_tau;
    const float sigma = tau;

    const int i = tid >> 1, h = tid & 1;
    unsigned long long rm[4];
    #pragma unroll
    for (int w = 0; w < 4; w++) rm[w] = g_rowMask[i][h*4 + w];
    unsigned long long cm[4];
    #pragma unroll
    for (int k = 0; k < 4; k++) cm[k] = g_colMask[tid + 128*k];

    float bc[4];
    #pragma unroll
    for (int r = 0; r < 4; r++) bc[r] = Xf[(r0 + r)*NCOMB + i];
    float4 ymr = make_float4(0.f, 0.f, 0.f, 0.f);
    if (h == 0) ym[i] = ymr;

    float4 z[4], x[4], yn[4];
    #pragma unroll
    for (int k = 0; k < 4; k++) {
        int j = tid + 128*k;
        float4 zz;
        zz.x = Zg[(size_t)(r0+0)*NSTR + j];
        zz.y = Zg[(size_t)(r0+1)*NSTR + j];
        zz.z = Zg[(size_t)(r0+2)*NSTR + j];
        zz.w = Zg[(size_t)(r0+3)*NSTR + j];
        z[k] = zz;
        x[k]  = make_float4(0.f,0.f,0.f,0.f);
        yn[k] = make_float4(0.f,0.f,0.f,0.f);
        xbar[j] = make_float4(0.f,0.f,0.f,0.f);
    }

    for (int it = 0; it < NITER; it++) {
        __syncthreads();   // xbar/ym settled

        // ---- step1: s = (S @ xbar) for this half-row, 4 batch rows at once
        float4 s = make_float4(0.f,0.f,0.f,0.f);
        #pragma unroll
        for (int w = 0; w < 4; w++) {
            unsigned long long mm = rm[w];
            const float4* xb = xbar + h*256 + w*64;
            while (mm) {
                int b = __ffsll(mm) - 1; mm &= mm - 1;
                float4 vv = xb[b];
                s.x += vv.x; s.y += vv.y; s.z += vv.z; s.w += vv.w;
            }
        }
        s.x += __shfl_xor_sync(0xffffffffu, s.x, 1);
        s.y += __shfl_xor_sync(0xffffffffu, s.y, 1);
        s.z += __shfl_xor_sync(0xffffffffu, s.z, 1);
        s.w += __shfl_xor_sync(0xffffffffu, s.w, 1);

        // ---- step2: yn = max(yn - sigma*xbar, 0)
        #pragma unroll
        for (int k = 0; k < 4; k++) {
            float4 xb = xbar[tid + 128*k];
            yn[k].x = fmaxf(yn[k].x - sigma*xb.x, 0.f);
            yn[k].y = fmaxf(yn[k].y - sigma*xb.y, 0.f);
            yn[k].z = fmaxf(yn[k].z - sigma*xb.z, 0.f);
            yn[k].w = fmaxf(yn[k].w - sigma*xb.w, 0.f);
        }
        if (h == 0) {
            ymr.x = fmaxf(ymr.x + sigma*(s.x - bc[0]), 0.f);
            ymr.y = fmaxf(ymr.y + sigma*(s.y - bc[1]), 0.f);
            ymr.z = fmaxf(ymr.z + sigma*(s.z - bc[2]), 0.f);
            ymr.w = fmaxf(ymr.w + sigma*(s.w - bc[3]), 0.f);
            ym[i] = ymr;
        }
        __syncthreads();   // ym visible

        // ---- step3: t = sum(ym over col mask) - yn ; prox
        float4 d[4];
        float4 dd = make_float4(0.f,0.f,0.f,0.f);
        #pragma unroll
        for (int k = 0; k < 4; k++) {
            float4 t = make_float4(0.f,0.f,0.f,0.f);
            unsigned long long mm = cm[k];
            while (mm) {
                int b = __ffsll(mm) - 1; mm &= mm - 1;
                float4 yv = ym[b];
                t.x += yv.x; t.y += yv.y; t.z += yv.z; t.w += yv.w;
            }
            float4 dv;
            dv.x = x[k].x - tau*(t.x - yn[k].x) + tau - z[k].x;
            dv.y = x[k].y - tau*(t.y - yn[k].y) + tau - z[k].y;
            dv.z = x[k].z - tau*(t.z - yn[k].z) + tau - z[k].z;
            dv.w = x[k].w - tau*(t.w - yn[k].w) + tau - z[k].w;
            d[k] = dv;
            dd.x = fmaf(dv.x, dv.x, dd.x);
            dd.y = fmaf(dv.y, dv.y, dd.y);
            dd.z = fmaf(dv.z, dv.z, dd.z);
            dd.w = fmaf(dv.w, dv.w, dd.w);
        }
        #pragma unroll
        for (int o = 16; o > 0; o >>= 1) {
            dd.x += __shfl_xor_sync(0xffffffffu, dd.x, o);
            dd.y += __shfl_xor_sync(0xffffffffu, dd.y, o);
            dd.z += __shfl_xor_sync(0xffffffffu, dd.z, o);
            dd.w += __shfl_xor_sync(0xffffffffu, dd.w, o);
        }
        if (lane == 0) red4[warp] = dd;
        __syncthreads();
        float4 t0 = red4[0], t1 = red4[1], t2 = red4[2], t3 = red4[3];
        float4 tot;
        tot.x = t0.x + t1.x + t2.x + t3.x;
        tot.y = t0.y + t1.y + t2.y + t3.y;
        tot.z = t0.z + t1.z + t2.z + t3.z;
        tot.w = t0.w + t1.w + t2.w + t3.w;
        float sc0 = fmaxf(1.f - tau / fmaxf(sqrtf(tot.x), 1e-12f), 0.f);
        float sc1 = fmaxf(1.f - tau / fmaxf(sqrtf(tot.y), 1e-12f), 0.f);
        float sc2 = fmaxf(1.f - tau / fmaxf(sqrtf(tot.z), 1e-12f), 0.f);
        float sc3 = fmaxf(1.f - tau / fmaxf(sqrtf(tot.w), 1e-12f), 0.f);

        #pragma unroll
        for (int k = 0; k < 4; k++) {
            float4 xn, nb;
            xn.x = fmaf(sc0, d[k].x, z[k].x);
            xn.y = fmaf(sc1, d[k].y, z[k].y);
            xn.z = fmaf(sc2, d[k].z, z[k].z);
            xn.w = fmaf(sc3, d[k].w, z[k].w);
            nb.x = 2.f*xn.x - x[k].x;
            nb.y = 2.f*xn.y - x[k].y;
            nb.z = 2.f*xn.z - x[k].z;
            nb.w = 2.f*xn.w - x[k].w;
            x[k] = xn;
            xbar[tid + 128*k] = nb;
        }
    }

    #pragma unroll
    for (int k = 0; k < 4; k++) {
        int j = tid + 128*k;
        out[(size_t)(r0+0)*NSTR + j] = x[k].x;
        out[(size_t)(r0+1)*NSTR + j] = x[k].y;
        out[(size_t)(r0+2)*NSTR + j] = x[k].z;
        out[(size_t)(r0+3)*NSTR + j] = x[k].w;
    }
}

// ---------------- launcher ----------------
extern "C" void kernel_launch(void* const* d_in, const int* in_sizes, int n_in,
                              void* d_out, int out_size)
{
    (void)in_sizes; (void)n_in; (void)out_size;
    const float* X  = (const float*)d_in[0];
    const float* W1 = (const float*)d_in[1];
    const float* b1 = (const float*)d_in[2];
    const float* W2 = (const float*)d_in[3];
    const float* b2 = (const float*)d_in[4];
    const float* W3 = (const float*)d_in[5];
    const float* b3 = (const float*)d_in[6];
    const float* S  = (const float*)d_in[7];
    float* out = (float*)d_out;

    float *H1, *H2, *Z;
    cudaGetSymbolAddress((void**)&H1, g_H1);
    cudaGetSymbolAddress((void**)&H2, g_H2);
    cudaGetSymbolAddress((void**)&Z,  g_Z);

    build_power<<<1, 512>>>(S);

    gemm_bias_relu<128,64,16,8,8><<<dim3(HID/64, BATCH/128), 128>>>(X,  W1, b1, H1, BATCH, HID,  NCOMB);
    gemm_bias_relu<128,64,16,8,8><<<dim3(HID/64, BATCH/128), 128>>>(H1, W2, b2, H2, BATCH, HID,  HID);
    gemm_bias_relu<128,64,16,8,8><<<dim3(NSTR/64, BATCH/128), 128>>>(H2, W3, b3, Z,  BATCH, NSTR, HID);

    pdhg_solver<<<BATCH/4, 128>>>(Z, X, out);
}

// round 8
// speedup vs baseline: 2.9780x; 1.8920x over previous
#include <cuda_runtime.h>
#include <cuda_bf16.h>
#include <cstdint>

#define BATCH 2048
#define NCOMB 64
#define NSTR  512
#define HID   1024
#define NITER 60
#define PITER 30

// ---------------- device scratch ----------------
__device__ float g_H1[BATCH * HID];
__device__ float g_H2[BATCH * HID];
__device__ float g_Z [BATCH * NSTR];
__device__ float g_tau;
__device__ unsigned long long g_rowMask[NCOMB][8];
__device__ unsigned long long g_colMask[NSTR];

// ELL gather schedules (built once; shared by all solver CTAs)
#define T1CAP 64
#define T3CAP 24
__device__ unsigned long long g_sched1[(T1CAP/4)*128];     // step1: xbar byte-offsets, 4 x u16 per u64
__device__ unsigned long long g_sched3[4][(T3CAP/4)*128];  // step3: ym byte-offsets per k
__device__ int g_T1[4];       // per-warp padded trip counts (multiple of 4)
__device__ int g_T3[16];      // [warp*4+k]

// ============ fp32 double-buffered tiled GEMM: C = relu(A@B + bias) ============
template<int BM, int BN, int BK, int TM, int TN>
__global__ void __launch_bounds__((BM/TM)*(BN/TN))
gemm_bias_relu(const float* __restrict__ A, const float* __restrict__ B,
               const float* __restrict__ bias, float* __restrict__ C,
               int M, int N, int K)
{
    constexpr int THREADS = (BM/TM)*(BN/TN);
    constexpr int LDA = BM + 4;
    constexpr int NA = (BM*BK/4)/THREADS;
    constexpr int NB = (BK*BN/4)/THREADS;

    __shared__ float As[2][BK*LDA];
    __shared__ float Bs[2][BK*BN];

    const int brow = blockIdx.y, bcol = blockIdx.x;
    A += (size_t)brow * BM * K;
    B += bcol * BN;
    C += (size_t)brow * BM * N + bcol * BN;

    const int tid  = threadIdx.x;
    const int tcol = tid % (BN/TN);
    const int trow = tid / (BN/TN);

    const int aRow    = tid / (BK/4);
    const int aCol4   = tid % (BK/4);
    const int aRowStr = THREADS/(BK/4);
    const int bRow    = tid / (BN/4);
    const int bCol4   = tid % (BN/4);
    const int bRowStr = THREADS/(BN/4);

    float4 aReg[NA], bReg[NB];
    float acc[TM][TN];
    #pragma unroll
    for (int i = 0; i < TM; i++)
        #pragma unroll
        for (int j = 0; j < TN; j++) acc[i][j] = 0.f;

    auto loadG = [&](int k0) {
        #pragma unroll
        for (int q = 0; q < NA; q++)
            aReg[q] = *reinterpret_cast<const float4*>(A + (size_t)(aRow + q*aRowStr)*K + k0 + aCol4*4);
        #pragma unroll
        for (int q = 0; q < NB; q++)
            bReg[q] = *reinterpret_cast<const float4*>(B + (size_t)(k0 + bRow + q*bRowStr)*N + bCol4*4);
    };
    auto storeS = [&](int buf) {
        #pragma unroll
        for (int q = 0; q < NA; q++) {
            int r = aRow + q*aRowStr;
            As[buf][(aCol4*4+0)*LDA + r] = aReg[q].x;
            As[buf][(aCol4*4+1)*LDA + r] = aReg[q].y;
            As[buf][(aCol4*4+2)*LDA + r] = aReg[q].z;
            As[buf][(aCol4*4+3)*LDA + r] = aReg[q].w;
        }
        #pragma unroll
        for (int q = 0; q < NB; q++)
            *reinterpret_cast<float4*>(&Bs[buf][(bRow + q*bRowStr)*BN + bCol4*4]) = bReg[q];
    };

    const int nt = K / BK;
    loadG(0);
    storeS(0);
    __syncthreads();

    for (int kt = 0; kt < nt; kt++) {
        const int cur = kt & 1;
        if (kt + 1 < nt) loadG((kt+1)*BK);

        #pragma unroll
        for (int k = 0; k < BK; k++) {
            float regM[TM], regN[TN];
            #pragma unroll
            for (int q = 0; q < TM/4; q++) {
                float4 m = *reinterpret_cast<const float4*>(&As[cur][k*LDA + trow*TM + q*4]);
                regM[q*4+0]=m.x; regM[q*4+1]=m.y; regM[q*4+2]=m.z; regM[q*4+3]=m.w;
            }
            #pragma unroll
            for (int q = 0; q < TN/4; q++) {
                float4 n = *reinterpret_cast<const float4*>(&Bs[cur][k*BN + tcol*TN + q*4]);
                regN[q*4+0]=n.x; regN[q*4+1]=n.y; regN[q*4+2]=n.z; regN[q*4+3]=n.w;
            }
            #pragma unroll
            for (int i = 0; i < TM; i++)
                #pragma unroll
                for (int j = 0; j < TN; j++)
                    acc[i][j] = fmaf(regM[i], regN[j], acc[i][j]);
        }

        if (kt + 1 < nt) { storeS(cur ^ 1); __syncthreads(); }
    }

    #pragma unroll
    for (int i = 0; i < TM; i++) {
        #pragma unroll
        for (int j = 0; j < TN; j += 4) {
            int col = tcol*TN + j;
            float4 bs = *reinterpret_cast<const float4*>(bias + bcol*BN + col);
            float4 o;
            o.x = fmaxf(acc[i][j+0] + bs.x, 0.f);
            o.y = fmaxf(acc[i][j+1] + bs.y, 0.f);
            o.z = fmaxf(acc[i][j+2] + bs.z, 0.f);
            o.w = fmaxf(acc[i][j+3] + bs.w, 0.f);
            *reinterpret_cast<float4*>(C + (size_t)(trow*TM + i)*N + col) = o;
        }
    }
}

// ============ fused: build bitmasks + power iteration (tau) ============
__global__ void __launch_bounds__(512) build_power(const float* __restrict__ S)
{
    __shared__ float v[NSTR];
    __shared__ float u[NCOMB];
    __shared__ float red[16];

    const int tid = threadIdx.x;
    const int lane = tid & 31, warp = tid >> 5;

    for (int i = warp; i < NCOMB; i += 16) {
        unsigned myb = 0;
        #pragma unroll
        for (int c = 0; c < 16; c++) {
            unsigned bal = __ballot_sync(0xffffffffu, S[i*NSTR + c*32 + lane] != 0.f);
            if (lane == c) myb = bal;
        }
        unsigned lo = __shfl_sync(0xffffffffu, myb, (lane & 7)*2);
        unsigned hi = __shfl_sync(0xffffffffu, myb, (lane & 7)*2 + 1);
        if (lane < 8)
            g_rowMask[i][lane] = (unsigned long long)lo | ((unsigned long long)hi << 32);
    }
    unsigned long long cmask = 0;
    for (int i = 0; i < NCOMB; i++)
        if (S[i*NSTR + tid] != 0.f) cmask |= (1ull << i);
    g_colMask[tid] = cmask;

    v[tid] = 0.04419417382415922f;
    __syncthreads();

    unsigned long long rm8[8];
    if (tid < NCOMB) {
        #pragma unroll
        for (int w = 0; w < 8; w++) rm8[w] = g_rowMask[tid][w];
    }
    __syncthreads();

    for (int step = 0; step <= PITER; step++) {
        if (tid < NCOMB) {
            float acc = 0.f;
            #pragma unroll
            for (int w = 0; w < 8; w++) {
                unsigned long long mm = rm8[w];
                while (mm) { int b = __ffsll(mm) - 1; mm &= mm - 1; acc += v[w*64 + b]; }
            }
            u[tid] = acc;
        }
        __syncthreads();
        float s = v[tid];
        {
            unsigned long long mm = cmask;
            while (mm) { int b = __ffsll(mm) - 1; mm &= mm - 1; s += u[b]; }
        }
        if (step < PITER) {
            float sq = s * s;
            #pragma unroll
            for (int o = 16; o > 0; o >>= 1) sq += __shfl_xor_sync(0xffffffffu, sq, o);
            if (lane == 0) red[warp] = sq;
            __syncthreads();
            float tot = 0.f;
            #pragma unroll
            for (int r = 0; r < 16; r++) tot += red[r];
            float nv = s / sqrtf(tot);
            __syncthreads();
            v[tid] = nv;
            __syncthreads();
        } else {
            float q = v[tid] * s;
            #pragma unroll
            for (int o = 16; o > 0; o >>= 1) q += __shfl_xor_sync(0xffffffffu, q, o);
            if (lane == 0) red[warp] = q;
            __syncthreads();
            if (tid == 0) {
                float tot = 0.f;
                for (int r = 0; r < 16; r++) tot += red[r];
                g_tau = 0.9f / sqrtf(tot);
            }
        }
    }
}

// ============ build conflict-aware ELL schedules (one block, 128 threads) =====
__global__ void __launch_bounds__(128) build_sched(const float* __restrict__ S)
{
    const int tid = threadIdx.x, lane = tid & 31, warp = tid >> 5;
    const int lr = lane & 7;

    // ---- step1 schedule: thread handles row i = tid>>1, half h = tid&1
    {
        const int i = tid >> 1, h = tid & 1;
        unsigned short loc[T1CAP];
        int cnt = 0;
        for (int j = h*256; j < h*256 + 256; j++)
            if (S[i*NSTR + j] != 0.f && cnt < T1CAP) loc[cnt++] = (unsigned short)j;

        int bc[8] = {0,0,0,0,0,0,0,0};
        for (int e = 0; e < cnt; e++) bc[((loc[e] & 7) - lr) & 7]++;
        int off[8]; off[0] = 0;
        for (int g = 1; g < 8; g++) off[g] = off[g-1] + bc[g-1];
        unsigned short srt[T1CAP];
        for (int e = 0; e < cnt; e++) {
            int kk = ((loc[e] & 7) - lr) & 7;
            srt[off[kk]++] = loc[e];
        }
        int mx = cnt;
        #pragma unroll
        for (int o = 16; o > 0; o >>= 1) mx = max(mx, __shfl_xor_sync(0xffffffffu, mx, o));
        mx = (mx + 3) & ~3;
        for (int e = cnt; e < mx; e++) srt[e] = (unsigned short)(512 + lr);
        for (int t4 = 0; t4 < mx/4; t4++) {
            unsigned long long w =
                 (unsigned long long)((unsigned)srt[4*t4+0] << 4)
              | ((unsigned long long)((unsigned)srt[4*t4+1] << 4) << 16)
              | ((unsigned long long)((unsigned)srt[4*t4+2] << 4) << 32)
              | ((unsigned long long)((unsigned)srt[4*t4+3] << 4) << 48);
            g_sched1[t4*128 + tid] = w;
        }
        if (lane == 0) g_T1[warp] = mx;
    }

    // ---- step3 schedules: thread handles columns j = tid + 128k
    for (int k = 0; k < 4; k++) {
        const int j = tid + 128*k;
        unsigned short loc[T3CAP];
        int cnt = 0;
        for (int b = 0; b < NCOMB; b++)
            if (S[b*NSTR + j] != 0.f && cnt < T3CAP) loc[cnt++] = (unsigned short)b;

        int bc[8] = {0,0,0,0,0,0,0,0};
        for (int e = 0; e < cnt; e++) bc[((loc[e] & 7) - lr) & 7]++;
        int off[8]; off[0] = 0;
        for (int g = 1; g < 8; g++) off[g] = off[g-1] + bc[g-1];
        unsigned short srt[T3CAP];
        for (int e = 0; e < cnt; e++) {
            int kk = ((loc[e] & 7) - lr) & 7;
            srt[off[kk]++] = loc[e];
        }
        int mx = cnt;
        #pragma unroll
        for (int o = 16; o > 0; o >>= 1) mx = max(mx, __shfl_xor_sync(0xffffffffu, mx, o));
        mx = (mx + 3) & ~3;
        for (int e = cnt; e < mx; e++) srt[e] = (unsigned short)(64 + lr);
        for (int t4 = 0; t4 < mx/4; t4++) {
            unsigned long long w =
                 (unsigned long long)((unsigned)srt[4*t4+0] << 4)
              | ((unsigned long long)((unsigned)srt[4*t4+1] << 4) << 16)
              | ((unsigned long long)((unsigned)srt[4*t4+2] << 4) << 32)
              | ((unsigned long long)((unsigned)srt[4*t4+3] << 4) << 48);
            g_sched3[k][t4*128 + tid] = w;
        }
        if (lane == 0) g_T3[warp*4 + k] = mx;
    }
}

// ============ PDHG solver: 4 batch rows per CTA, scheduled float4 gathers =====
__global__ void __launch_bounds__(128) pdhg_solver(const float* __restrict__ Zg,
                                                   const float* __restrict__ Xf,
                                                   float* __restrict__ out)
{
    const int r0  = blockIdx.x * 4;
    const int tid = threadIdx.x;
    const int lane = tid & 31, warp = tid >> 5;

    __shared__ float4 xbar[520];   // 512 real + 8 zero pads (rotated)
    __shared__ float4 ym[72];      // 64 real + 8 zero pads
    __shared__ float4 red4[4];

    const unsigned xb_base = (unsigned)__cvta_generic_to_shared(xbar);
    const unsigned ym_base = (unsigned)__cvta_generic_to_shared(ym);

    const float tau = g_tau;
    const float sigma = tau;

    const int i = tid >> 1, h = tid & 1;
    const int T1 = g_T1[warp] >> 2;
    int T3[4];
    {
        int4 tv = *reinterpret_cast<const int4*>(g_T3 + warp*4);
        T3[0] = tv.x >> 2; T3[1] = tv.y >> 2; T3[2] = tv.z >> 2; T3[3] = tv.w >> 2;
    }

    float bc0 = Xf[(r0+0)*NCOMB + i];
    float bc1 = Xf[(r0+1)*NCOMB + i];
    float bc2 = Xf[(r0+2)*NCOMB + i];
    float bc3 = Xf[(r0+3)*NCOMB + i];
    float4 ymr = make_float4(0.f,0.f,0.f,0.f);
    if (h == 0) ym[i] = ymr;
    if (tid < 8)  xbar[512 + tid] = make_float4(0.f,0.f,0.f,0.f);
    if (tid < 8)  ym[64 + tid]   = make_float4(0.f,0.f,0.f,0.f);

    float4 z[4], x[4], yn[4], xb_own[4];
    #pragma unroll
    for (int k = 0; k < 4; k++) {
        int j = tid + 128*k;
        float4 zz;
        zz.x = Zg[(size_t)(r0+0)*NSTR + j];
        zz.y = Zg[(size_t)(r0+1)*NSTR + j];
        zz.z = Zg[(size_t)(r0+2)*NSTR + j];
        zz.w = Zg[(size_t)(r0+3)*NSTR + j];
        z[k] = zz;
        x[k]  = make_float4(0.f,0.f,0.f,0.f);
        yn[k] = make_float4(0.f,0.f,0.f,0.f);
        xb_own[k] = make_float4(0.f,0.f,0.f,0.f);
        xbar[j] = make_float4(0.f,0.f,0.f,0.f);
    }

    for (int it = 0; it < NITER; it++) {
        __syncthreads();   // xbar stores + red4 reads settled

        // ---- step1: s = (S @ xbar) for half-row (i,h), 4 batch rows packed
        unsigned long long sxy = 0ull, szw = 0ull;   // bits of {0.f,0.f}
        const unsigned long long* sp1 = g_sched1 + tid;
        #pragma unroll 2
        for (int t4 = 0; t4 < T1; t4++) {
            unsigned long long wd = __ldg(sp1 + t4*128);
            #pragma unroll
            for (int q = 0; q < 4; q++) {
                unsigned off = (unsigned)(wd >> (16*q)) & 0xffffu;
                unsigned long long vlo, vhi;
                asm volatile("ld.shared.v2.b64 {%0,%1}, [%2];"
                             : "=l"(vlo), "=l"(vhi) : "r"(xb_base + off));
                asm("add.rn.f32x2 %0, %0, %1;" : "+l"(sxy) : "l"(vlo));
                asm("add.rn.f32x2 %0, %0, %1;" : "+l"(szw) : "l"(vhi));
            }
        }
        float s0, s1, s2, s3;
        asm("mov.b64 {%0,%1}, %2;" : "=f"(s0), "=f"(s1) : "l"(sxy));
        asm("mov.b64 {%0,%1}, %2;" : "=f"(s2), "=f"(s3) : "l"(szw));
        s0 += __shfl_xor_sync(0xffffffffu, s0, 1);
        s1 += __shfl_xor_sync(0xffffffffu, s1, 1);
        s2 += __shfl_xor_sync(0xffffffffu, s2, 1);
        s3 += __shfl_xor_sync(0xffffffffu, s3, 1);

        // ---- step2: yn = max(yn - sigma*xbar, 0) using register copy of own xbar
        #pragma unroll
        for (int k = 0; k < 4; k++) {
            yn[k].x = fmaxf(fmaf(-sigma, xb_own[k].x, yn[k].x), 0.f);
            yn[k].y = fmaxf(fmaf(-sigma, xb_own[k].y, yn[k].y), 0.f);
            yn[k].z = fmaxf(fmaf(-sigma, xb_own[k].z, yn[k].z), 0.f);
            yn[k].w = fmaxf(fmaf(-sigma, xb_own[k].w, yn[k].w), 0.f);
        }
        if (h == 0) {
            ymr.x = fmaxf(fmaf(sigma, s0 - bc0, ymr.x), 0.f);
            ymr.y = fmaxf(fmaf(sigma, s1 - bc1, ymr.y), 0.f);
            ymr.z = fmaxf(fmaf(sigma, s2 - bc2, ymr.z), 0.f);
            ymr.w = fmaxf(fmaf(sigma, s3 - bc3, ymr.w), 0.f);
            ym[i] = ymr;
        }
        __syncthreads();   // ym visible

        // ---- step3: t = sum(ym over column) - yn ; prox
        float4 d[4];
        float4 dd = make_float4(0.f,0.f,0.f,0.f);
        #pragma unroll
        for (int k = 0; k < 4; k++) {
            unsigned long long txy = 0ull, tzw = 0ull;
            const unsigned long long* sp3 = g_sched3[k] + tid;
            for (int t4 = 0; t4 < T3[k]; t4++) {
                unsigned long long wd = __ldg(sp3 + t4*128);
                #pragma unroll
                for (int q = 0; q < 4; q++) {
                    unsigned off = (unsigned)(wd >> (16*q)) & 0xffffu;
                    unsigned long long vlo, vhi;
                    asm volatile("ld.shared.v2.b64 {%0,%1}, [%2];"
                                 : "=l"(vlo), "=l"(vhi) : "r"(ym_base + off));
                    asm("add.rn.f32x2 %0, %0, %1;" : "+l"(txy) : "l"(vlo));
                    asm("add.rn.f32x2 %0, %0, %1;" : "+l"(tzw) : "l"(vhi));
                }
            }
            float t0, t1, t2, t3;
            asm("mov.b64 {%0,%1}, %2;" : "=f"(t0), "=f"(t1) : "l"(txy));
            asm("mov.b64 {%0,%1}, %2;" : "=f"(t2), "=f"(t3) : "l"(tzw));
            float4 dv;
            dv.x = x[k].x - tau*(t0 - yn[k].x) + tau - z[k].x;
            dv.y = x[k].y - tau*(t1 - yn[k].y) + tau - z[k].y;
            dv.z = x[k].z - tau*(t2 - yn[k].z) + tau - z[k].z;
            dv.w = x[k].w - tau*(t3 - yn[k].w) + tau - z[k].w;
            d[k] = dv;
            dd.x = fmaf(dv.x, dv.x, dd.x);
            dd.y = fmaf(dv.y, dv.y, dd.y);
            dd.z = fmaf(dv.z, dv.z, dd.z);
            dd.w = fmaf(dv.w, dv.w, dd.w);
        }
        #pragma unroll
        for (int o = 16; o > 0; o >>= 1) {
            dd.x += __shfl_xor_sync(0xffffffffu, dd.x, o);
            dd.y += __shfl_xor_sync(0xffffffffu, dd.y, o);
            dd.z += __shfl_xor_sync(0xffffffffu, dd.z, o);
            dd.w += __shfl_xor_sync(0xffffffffu, dd.w, o);
        }
        if (lane == 0) red4[warp] = dd;
        __syncthreads();
        float4 t0v = red4[0], t1v = red4[1], t2v = red4[2], t3v = red4[3];
        float sc0 = fmaxf(1.f - tau / fmaxf(sqrtf(t0v.x + t1v.x + t2v.x + t3v.x), 1e-12f), 0.f);
        float sc1 = fmaxf(1.f - tau / fmaxf(sqrtf(t0v.y + t1v.y + t2v.y + t3v.y), 1e-12f), 0.f);
        float sc2 = fmaxf(1.f - tau / fmaxf(sqrtf(t0v.z + t1v.z + t2v.z + t3v.z), 1e-12f), 0.f);
        float sc3 = fmaxf(1.f - tau / fmaxf(sqrtf(t0v.w + t1v.w + t2v.w + t3v.w), 1e-12f), 0.f);

        #pragma unroll
        for (int k = 0; k < 4; k++) {
            float4 xn, nb;
            xn.x = fmaf(sc0, d[k].x, z[k].x);
            xn.y = fmaf(sc1, d[k].y, z[k].y);
            xn.z = fmaf(sc2, d[k].z, z[k].z);
            xn.w = fmaf(sc3, d[k].w, z[k].w);
            nb.x = 2.f*xn.x - x[k].x;
            nb.y = 2.f*xn.y - x[k].y;
            nb.z = 2.f*xn.z - x[k].z;
            nb.w = 2.f*xn.w - x[k].w;
            x[k] = xn;
            xb_own[k] = nb;
            xbar[tid + 128*k] = nb;
        }
    }

    #pragma unroll
    for (int k = 0; k < 4; k++) {
        int j = tid + 128*k;
        out[(size_t)(r0+0)*NSTR + j] = x[k].x;
        out[(size_t)(r0+1)*NSTR + j] = x[k].y;
        out[(size_t)(r0+2)*NSTR + j] = x[k].z;
        out[(size_t)(r0+3)*NSTR + j] = x[k].w;
    }
}

// ---------------- launcher ----------------
extern "C" void kernel_launch(void* const* d_in, const int* in_sizes, int n_in,
                              void* d_out, int out_size)
{
    (void)in_sizes; (void)n_in; (void)out_size;
    const float* X  = (const float*)d_in[0];
    const float* W1 = (const float*)d_in[1];
    const float* b1 = (const float*)d_in[2];
    const float* W2 = (const float*)d_in[3];
    const float* b2 = (const float*)d_in[4];
    const float* W3 = (const float*)d_in[5];
    const float* b3 = (const float*)d_in[6];
    const float* S  = (const float*)d_in[7];
    float* out = (float*)d_out;

    float *H1, *H2, *Z;
    cudaGetSymbolAddress((void**)&H1, g_H1);
    cudaGetSymbolAddress((void**)&H2, g_H2);
    cudaGetSymbolAddress((void**)&Z,  g_Z);

    build_power<<<1, 512>>>(S);
    build_sched<<<1, 128>>>(S);

    gemm_bias_relu<64,64,16,8,4><<<dim3(HID/64,  BATCH/64), 128>>>(X,  W1, b1, H1, BATCH, HID,  NCOMB);
    gemm_bias_relu<64,64,16,8,4><<<dim3(HID/64,  BATCH/64), 128>>>(H1, W2, b2, H2, BATCH, HID,  HID);
    gemm_bias_relu<64,64,16,8,4><<<dim3(NSTR/64, BATCH/64), 128>>>(H2, W3, b3, Z,  BATCH, NSTR, HID);

    pdhg_solver<<<BATCH/4, 128>>>(Z, X, out);
}